// round 1
// baseline (speedup 1.0000x reference)
#include <cuda_runtime.h>
#include <cuda_bf16.h>

#define USER_NUM 200000
#define ITEM_NUM 100000
#define EMB 64

// Scratch (allocation-free rule: __device__ globals)
__device__ float g_agg[(size_t)USER_NUM * EMB];   // 51.2 MB
__device__ float g_U[(size_t)USER_NUM * EMB];     // 51.2 MB

// ---------------------------------------------------------------------------
// Zero-fill (grid-stride float4)
// ---------------------------------------------------------------------------
__global__ void zero_kernel(float4* __restrict__ p, int n4) {
    int i = blockIdx.x * blockDim.x + threadIdx.x;
    if (i < n4) p[i] = make_float4(0.f, 0.f, 0.f, 0.f);
}

// ---------------------------------------------------------------------------
// COO SpMM: out[row] += val * X[col]   (16 threads per edge, float4 per thread)
// Uses red.global.add.v4.f32 (sm_90+) — fire-and-forget vector reduction.
// ---------------------------------------------------------------------------
__global__ void spmm_kernel(const int* __restrict__ rows,
                            const int* __restrict__ cols,
                            const float* __restrict__ vals,
                            const float4* __restrict__ X4,
                            float* __restrict__ out,
                            int ne) {
    long long t = (long long)blockIdx.x * blockDim.x + threadIdx.x;
    int e = (int)(t >> 4);
    int g = (int)(t & 15);
    if (e >= ne) return;
    int   r = rows[e];
    int   c = cols[e];
    float v = vals[e];
    float4 x = X4[(long long)c * 16 + g];
    float4 y = make_float4(v * x.x, v * x.y, v * x.z, v * x.w);
    float* dst = out + ((long long)r * EMB + g * 4);
#if __CUDA_ARCH__ >= 900
    asm volatile("red.global.add.v4.f32 [%0], {%1,%2,%3,%4};"
                 :: "l"(dst), "f"(y.x), "f"(y.y), "f"(y.z), "f"(y.w)
                 : "memory");
#else
    atomicAdd(dst + 0, y.x); atomicAdd(dst + 1, y.y);
    atomicAdd(dst + 2, y.z); atomicAdd(dst + 3, y.w);
#endif
}

// ---------------------------------------------------------------------------
// Fused GEMM + bias + ReLU:
//   out[r, o] = relu( sum_k h[r,k] * W[o,k] + b[o] ),  h = concat(agg, U)
// Block: 64 rows x 64 outs, 256 threads, 4x4 register micro-tile.
// Shared: hs[64][132] (padded), ws[128][68] (W transposed to [k][o]).
// ---------------------------------------------------------------------------
#define HS_STRIDE 132
#define WS_STRIDE 68
#define GEMM_SMEM ((64 * HS_STRIDE + 128 * WS_STRIDE) * 4)   // 68,608 B

__global__ void __launch_bounds__(256, 3)
gemm_relu_kernel(const float4* __restrict__ agg4,
                 const float4* __restrict__ u4,
                 const float4* __restrict__ W4,   // [64][32] float4 view of [64][128]
                 const float*  __restrict__ bias,
                 float4* __restrict__ out4) {
    extern __shared__ float smem[];
    float* hs = smem;                       // 64 * 132
    float* ws = smem + 64 * HS_STRIDE;      // 128 * 68

    int tid = threadIdx.x;
    long long block_row = (long long)blockIdx.x * 64;

    // Load h tile: 64 rows x 32 float4 (first 16 from agg, next 16 from U)
    #pragma unroll
    for (int i = tid; i < 64 * 32; i += 256) {
        int r = i >> 5, c = i & 31;
        long long grow = block_row + r;
        float4 v = (c < 16) ? agg4[grow * 16 + c] : u4[grow * 16 + (c - 16)];
        *(float4*)&hs[r * HS_STRIDE + c * 4] = v;
    }
    // Load + transpose W into ws[k][o] (conflict-free shared stores over o)
    #pragma unroll
    for (int i = tid; i < 64 * 32; i += 256) {
        int o = i & 63, c = i >> 6;
        float4 w = W4[o * 32 + c];
        ws[(4 * c + 0) * WS_STRIDE + o] = w.x;
        ws[(4 * c + 1) * WS_STRIDE + o] = w.y;
        ws[(4 * c + 2) * WS_STRIDE + o] = w.z;
        ws[(4 * c + 3) * WS_STRIDE + o] = w.w;
    }
    __syncthreads();

    int tx = tid & 15, ty = tid >> 4;
    int o0 = tx * 4;
    float acc[4][4] = {};

    #pragma unroll 4
    for (int k4 = 0; k4 < 32; k4++) {
        float4 wv[4];
        #pragma unroll
        for (int j = 0; j < 4; j++)
            wv[j] = *(const float4*)&ws[(4 * k4 + j) * WS_STRIDE + o0];
        #pragma unroll
        for (int ri = 0; ri < 4; ri++) {
            int r = ty * 4 + ri;
            float4 hv = *(const float4*)&hs[r * HS_STRIDE + k4 * 4];
            acc[ri][0] += hv.x * wv[0].x + hv.y * wv[1].x + hv.z * wv[2].x + hv.w * wv[3].x;
            acc[ri][1] += hv.x * wv[0].y + hv.y * wv[1].y + hv.z * wv[2].y + hv.w * wv[3].y;
            acc[ri][2] += hv.x * wv[0].z + hv.y * wv[1].z + hv.z * wv[2].z + hv.w * wv[3].z;
            acc[ri][3] += hv.x * wv[0].w + hv.y * wv[1].w + hv.z * wv[2].w + hv.w * wv[3].w;
        }
    }

    float b0 = bias[o0 + 0], b1 = bias[o0 + 1], b2 = bias[o0 + 2], b3 = bias[o0 + 3];
    #pragma unroll
    for (int ri = 0; ri < 4; ri++) {
        long long r = block_row + ty * 4 + ri;
        float4 v;
        v.x = fmaxf(acc[ri][0] + b0, 0.f);
        v.y = fmaxf(acc[ri][1] + b1, 0.f);
        v.z = fmaxf(acc[ri][2] + b2, 0.f);
        v.w = fmaxf(acc[ri][3] + b3, 0.f);
        out4[r * 16 + tx] = v;
    }
}

// ---------------------------------------------------------------------------
// Launch
// ---------------------------------------------------------------------------
extern "C" void kernel_launch(void* const* d_in, const int* in_sizes, int n_in,
                              void* d_out, int out_size) {
    const float* user_emb = (const float*)d_in[0];
    const float* item_emb = (const float*)d_in[1];
    const float* W        = (const float*)d_in[2];   // [2][64][128]
    const float* b        = (const float*)d_in[3];   // [2][64]
    const int*   s_rows   = (const int*)  d_in[4];
    const int*   s_cols   = (const int*)  d_in[5];
    const float* s_vals   = (const float*)d_in[6];
    const int*   r_rows   = (const int*)  d_in[7];
    const int*   r_cols   = (const int*)  d_in[8];
    const float* r_vals   = (const float*)d_in[9];
    int ne_s = in_sizes[4];
    int ne_r = in_sizes[7];

    float* out_user = (float*)d_out;
    float* out_item = out_user + (size_t)USER_NUM * EMB;

    float *agg, *U1;
    cudaGetSymbolAddress((void**)&agg, g_agg);
    cudaGetSymbolAddress((void**)&U1,  g_U);

    cudaFuncSetAttribute(gemm_relu_kernel,
                         cudaFuncAttributeMaxDynamicSharedMemorySize, GEMM_SMEM);

    const int n4      = USER_NUM * (EMB / 4);                   // 3.2M float4
    const int zb      = (n4 + 255) / 256;
    const int sb_s    = (int)(((long long)ne_s * 16 + 255) / 256);
    const int sb_r    = (int)(((long long)ne_r * 16 + 255) / 256);
    const int gemm_gb = USER_NUM / 64;                          // 3125

    // Layer 0: agg = S @ U0 ; U1 = relu([agg, U0] @ W0^T + b0)
    zero_kernel<<<zb, 256>>>((float4*)agg, n4);
    spmm_kernel<<<sb_s, 256>>>(s_rows, s_cols, s_vals, (const float4*)user_emb, agg, ne_s);
    gemm_relu_kernel<<<gemm_gb, 256, GEMM_SMEM>>>((const float4*)agg, (const float4*)user_emb,
                                                  (const float4*)W, b, (float4*)U1);

    // Layer 1: agg = S @ U1 ; U2 = relu([agg, U1] @ W1^T + b1) -> out_user
    zero_kernel<<<zb, 256>>>((float4*)agg, n4);
    spmm_kernel<<<sb_s, 256>>>(s_rows, s_cols, s_vals, (const float4*)U1, agg, ne_s);
    gemm_relu_kernel<<<gemm_gb, 256, GEMM_SMEM>>>((const float4*)agg, (const float4*)U1,
                                                  (const float4*)(W + 64 * 128), b + 64,
                                                  (float4*)out_user);

    // user_all = U2 + R @ V  (atomic add directly into out_user)
    spmm_kernel<<<sb_r, 256>>>(r_rows, r_cols, r_vals, (const float4*)item_emb, out_user, ne_r);

    // item_all = V
    cudaMemcpyAsync(out_item, item_emb, (size_t)ITEM_NUM * EMB * sizeof(float),
                    cudaMemcpyDeviceToDevice, 0);
}

// round 2
// speedup vs baseline: 1.4464x; 1.4464x over previous
#include <cuda_runtime.h>
#include <cuda_bf16.h>

#define USER_NUM 200000
#define ITEM_NUM 100000
#define EMB 64
#define MAX_NE 3200000

// ---------------------------------------------------------------------------
// Scratch (__device__ globals; no allocation allowed)
// ---------------------------------------------------------------------------
__device__ float g_agg[(size_t)USER_NUM * EMB];     // 51.2 MB
__device__ float g_U[(size_t)USER_NUM * EMB];       // 51.2 MB
__device__ int   g_csr_col[MAX_NE];                 // 12.8 MB
__device__ float g_csr_val[MAX_NE];                 // 12.8 MB
__device__ int   g_cnt[USER_NUM];
__device__ int   g_rs[USER_NUM];                    // row start
__device__ int   g_cur[USER_NUM];                   // scatter cursor
__device__ int   g_bsum[256];                       // block sums for scan

// ---------------------------------------------------------------------------
// CSR build: zero counts -> histogram -> 2-level exclusive scan -> scatter
// ---------------------------------------------------------------------------
__global__ void zero_int_kernel(int* __restrict__ p, int n) {
    int i = blockIdx.x * blockDim.x + threadIdx.x;
    if (i < n) p[i] = 0;
}

__global__ void hist_kernel(const int* __restrict__ rows, int* __restrict__ cnt, int ne) {
    int i = blockIdx.x * blockDim.x + threadIdx.x;
    if (i < ne) atomicAdd(&cnt[rows[i]], 1);
}

__device__ __forceinline__ int warp_excl_scan(int v, int lane, int* total) {
    int x = v;
    #pragma unroll
    for (int d = 1; d < 32; d <<= 1) {
        int y = __shfl_up_sync(0xffffffffu, x, d);
        if (lane >= d) x += y;
    }
    *total = __shfl_sync(0xffffffffu, x, 31);
    return x - v;
}

// K1: per-block (1024 elems) sum
__global__ void block_sum_kernel(const int* __restrict__ cnt, int* __restrict__ bsum, int n) {
    __shared__ int wsum[8];
    int tid = threadIdx.x, lane = tid & 31, wid = tid >> 5;
    int base = blockIdx.x * 1024 + tid * 4;
    int s = 0;
    #pragma unroll
    for (int j = 0; j < 4; j++) { int idx = base + j; if (idx < n) s += cnt[idx]; }
    int tot; warp_excl_scan(s, lane, &tot);
    if (lane == 31) wsum[wid] = tot;
    __syncthreads();
    if (tid == 0) {
        int t = 0;
        #pragma unroll
        for (int w = 0; w < 8; w++) t += wsum[w];
        bsum[blockIdx.x] = t;
    }
}

// K2: exclusive scan of block sums (single block, nb <= 256)
__global__ void scan_bsum_kernel(int* __restrict__ bsum, int nb) {
    __shared__ int wsum[8];
    int tid = threadIdx.x, lane = tid & 31, wid = tid >> 5;
    int v = (tid < nb) ? bsum[tid] : 0;
    int wtot; int ex = warp_excl_scan(v, lane, &wtot);
    if (lane == 31) wsum[wid] = wtot;
    __syncthreads();
    if (wid == 0) {
        int t = (lane < 8) ? wsum[lane] : 0;
        int tt; int e = warp_excl_scan(t, lane, &tt);
        if (lane < 8) wsum[lane] = e;
    }
    __syncthreads();
    if (tid < nb) bsum[tid] = wsum[wid] + ex;
}

// K3: block-local exclusive scan + block offset -> row_start & cursor
__global__ void scan_block_kernel(const int* __restrict__ cnt, const int* __restrict__ boff,
                                  int* __restrict__ rs, int* __restrict__ cur, int n) {
    __shared__ int wsum[8];
    int tid = threadIdx.x, lane = tid & 31, wid = tid >> 5;
    int base = blockIdx.x * 1024 + tid * 4;
    int v[4]; int s = 0;
    #pragma unroll
    for (int j = 0; j < 4; j++) { int idx = base + j; v[j] = (idx < n) ? cnt[idx] : 0; s += v[j]; }
    int wtot; int ex = warp_excl_scan(s, lane, &wtot);
    if (lane == 31) wsum[wid] = wtot;
    __syncthreads();
    if (wid == 0) {
        int t = (lane < 8) ? wsum[lane] : 0;
        int tt; int e = warp_excl_scan(t, lane, &tt);
        if (lane < 8) wsum[lane] = e;
    }
    __syncthreads();
    int off = boff[blockIdx.x] + wsum[wid] + ex;
    #pragma unroll
    for (int j = 0; j < 4; j++) {
        int idx = base + j;
        if (idx < n) { rs[idx] = off; cur[idx] = off; off += v[j]; }
    }
}

__global__ void scatter_kernel(const int* __restrict__ rows, const int* __restrict__ cols,
                               const float* __restrict__ vals, int* __restrict__ cur,
                               int* __restrict__ ccol, float* __restrict__ cval, int ne) {
    int i = blockIdx.x * blockDim.x + threadIdx.x;
    if (i >= ne) return;
    int r = rows[i];
    int p = atomicAdd(&cur[r], 1);
    ccol[p] = cols[i];
    cval[p] = vals[i];
}

// ---------------------------------------------------------------------------
// CSR SpMM: 16 threads per output row, register accumulation, no atomics.
// accumulate: 0 -> overwrite out, 1 -> out += sum
// ---------------------------------------------------------------------------
__global__ void __launch_bounds__(256)
spmm_csr_kernel(const int* __restrict__ rs, const int* __restrict__ cnt,
                const int* __restrict__ ccol, const float* __restrict__ cval,
                const float4* __restrict__ X4, float4* __restrict__ out4,
                int accumulate) {
    long long t = (long long)blockIdx.x * blockDim.x + threadIdx.x;
    int row = (int)(t >> 4);
    int g   = (int)(t & 15);
    if (row >= USER_NUM) return;
    int s = rs[row];
    int e = s + cnt[row];
    float4 acc;
    if (accumulate) acc = out4[(long long)row * 16 + g];
    else            acc = make_float4(0.f, 0.f, 0.f, 0.f);
    for (int i = s; i < e; i++) {
        int   c = __ldg(&ccol[i]);
        float v = __ldg(&cval[i]);
        float4 x = X4[(long long)c * 16 + g];
        acc.x += v * x.x; acc.y += v * x.y; acc.z += v * x.z; acc.w += v * x.w;
    }
    out4[(long long)row * 16 + g] = acc;
}

// ---------------------------------------------------------------------------
// Fused GEMM + bias + ReLU (unchanged, known good)
// ---------------------------------------------------------------------------
#define HS_STRIDE 132
#define WS_STRIDE 68
#define GEMM_SMEM ((64 * HS_STRIDE + 128 * WS_STRIDE) * 4)

__global__ void __launch_bounds__(256, 3)
gemm_relu_kernel(const float4* __restrict__ agg4,
                 const float4* __restrict__ u4,
                 const float4* __restrict__ W4,
                 const float*  __restrict__ bias,
                 float4* __restrict__ out4) {
    extern __shared__ float smem[];
    float* hs = smem;
    float* ws = smem + 64 * HS_STRIDE;

    int tid = threadIdx.x;
    long long block_row = (long long)blockIdx.x * 64;

    #pragma unroll
    for (int i = tid; i < 64 * 32; i += 256) {
        int r = i >> 5, c = i & 31;
        long long grow = block_row + r;
        float4 v = (c < 16) ? agg4[grow * 16 + c] : u4[grow * 16 + (c - 16)];
        *(float4*)&hs[r * HS_STRIDE + c * 4] = v;
    }
    #pragma unroll
    for (int i = tid; i < 64 * 32; i += 256) {
        int o = i & 63, c = i >> 6;
        float4 w = W4[o * 32 + c];
        ws[(4 * c + 0) * WS_STRIDE + o] = w.x;
        ws[(4 * c + 1) * WS_STRIDE + o] = w.y;
        ws[(4 * c + 2) * WS_STRIDE + o] = w.z;
        ws[(4 * c + 3) * WS_STRIDE + o] = w.w;
    }
    __syncthreads();

    int tx = tid & 15, ty = tid >> 4;
    int o0 = tx * 4;
    float acc[4][4] = {};

    #pragma unroll 4
    for (int k4 = 0; k4 < 32; k4++) {
        float4 wv[4];
        #pragma unroll
        for (int j = 0; j < 4; j++)
            wv[j] = *(const float4*)&ws[(4 * k4 + j) * WS_STRIDE + o0];
        #pragma unroll
        for (int ri = 0; ri < 4; ri++) {
            int r = ty * 4 + ri;
            float4 hv = *(const float4*)&hs[r * HS_STRIDE + k4 * 4];
            acc[ri][0] += hv.x * wv[0].x + hv.y * wv[1].x + hv.z * wv[2].x + hv.w * wv[3].x;
            acc[ri][1] += hv.x * wv[0].y + hv.y * wv[1].y + hv.z * wv[2].y + hv.w * wv[3].y;
            acc[ri][2] += hv.x * wv[0].z + hv.y * wv[1].z + hv.z * wv[2].z + hv.w * wv[3].z;
            acc[ri][3] += hv.x * wv[0].w + hv.y * wv[1].w + hv.z * wv[2].w + hv.w * wv[3].w;
        }
    }

    float b0 = bias[o0 + 0], b1 = bias[o0 + 1], b2 = bias[o0 + 2], b3 = bias[o0 + 3];
    #pragma unroll
    for (int ri = 0; ri < 4; ri++) {
        long long r = block_row + ty * 4 + ri;
        float4 v;
        v.x = fmaxf(acc[ri][0] + b0, 0.f);
        v.y = fmaxf(acc[ri][1] + b1, 0.f);
        v.z = fmaxf(acc[ri][2] + b2, 0.f);
        v.w = fmaxf(acc[ri][3] + b3, 0.f);
        out4[r * 16 + tx] = v;
    }
}

// ---------------------------------------------------------------------------
// Launch
// ---------------------------------------------------------------------------
static void build_csr(const int* rows, const int* cols, const float* vals, int ne,
                      int* cnt, int* rs, int* cur, int* bsum, int* ccol, float* cval) {
    const int nb_scan = (USER_NUM + 1023) / 1024;          // 196
    const int eb = (ne + 255) / 256;
    zero_int_kernel<<<(USER_NUM + 255) / 256, 256>>>(cnt, USER_NUM);
    hist_kernel<<<eb, 256>>>(rows, cnt, ne);
    block_sum_kernel<<<nb_scan, 256>>>(cnt, bsum, USER_NUM);
    scan_bsum_kernel<<<1, 256>>>(bsum, nb_scan);
    scan_block_kernel<<<nb_scan, 256>>>(cnt, bsum, rs, cur, USER_NUM);
    scatter_kernel<<<eb, 256>>>(rows, cols, vals, cur, ccol, cval, ne);
}

extern "C" void kernel_launch(void* const* d_in, const int* in_sizes, int n_in,
                              void* d_out, int out_size) {
    const float* user_emb = (const float*)d_in[0];
    const float* item_emb = (const float*)d_in[1];
    const float* W        = (const float*)d_in[2];
    const float* b        = (const float*)d_in[3];
    const int*   s_rows   = (const int*)  d_in[4];
    const int*   s_cols   = (const int*)  d_in[5];
    const float* s_vals   = (const float*)d_in[6];
    const int*   r_rows   = (const int*)  d_in[7];
    const int*   r_cols   = (const int*)  d_in[8];
    const float* r_vals   = (const float*)d_in[9];
    int ne_s = in_sizes[4];
    int ne_r = in_sizes[7];

    float* out_user = (float*)d_out;
    float* out_item = out_user + (size_t)USER_NUM * EMB;

    float *agg, *U1, *cval;
    int *cnt, *rs, *cur, *bsum, *ccol;
    cudaGetSymbolAddress((void**)&agg,  g_agg);
    cudaGetSymbolAddress((void**)&U1,   g_U);
    cudaGetSymbolAddress((void**)&cnt,  g_cnt);
    cudaGetSymbolAddress((void**)&rs,   g_rs);
    cudaGetSymbolAddress((void**)&cur,  g_cur);
    cudaGetSymbolAddress((void**)&bsum, g_bsum);
    cudaGetSymbolAddress((void**)&ccol, g_csr_col);
    cudaGetSymbolAddress((void**)&cval, g_csr_val);

    cudaFuncSetAttribute(gemm_relu_kernel,
                         cudaFuncAttributeMaxDynamicSharedMemorySize, GEMM_SMEM);

    const int spmm_gb = (USER_NUM * 16 + 255) / 256;   // 12500
    const int gemm_gb = USER_NUM / 64;                 // 3125

    // ---- CSR(S) build (used by both layers) ----
    build_csr(s_rows, s_cols, s_vals, ne_s, cnt, rs, cur, bsum, ccol, cval);

    // Layer 0
    spmm_csr_kernel<<<spmm_gb, 256>>>(rs, cnt, ccol, cval, (const float4*)user_emb,
                                      (float4*)agg, 0);
    gemm_relu_kernel<<<gemm_gb, 256, GEMM_SMEM>>>((const float4*)agg, (const float4*)user_emb,
                                                  (const float4*)W, b, (float4*)U1);
    // Layer 1
    spmm_csr_kernel<<<spmm_gb, 256>>>(rs, cnt, ccol, cval, (const float4*)U1,
                                      (float4*)agg, 0);
    gemm_relu_kernel<<<gemm_gb, 256, GEMM_SMEM>>>((const float4*)agg, (const float4*)U1,
                                                  (const float4*)(W + 64 * 128), b + 64,
                                                  (float4*)out_user);

    // ---- CSR(R) build + final accumulate SpMM ----
    build_csr(r_rows, r_cols, r_vals, ne_r, cnt, rs, cur, bsum, ccol, cval);
    spmm_csr_kernel<<<spmm_gb, 256>>>(rs, cnt, ccol, cval, (const float4*)item_emb,
                                      (float4*)out_user, 1);

    // item_all = V
    cudaMemcpyAsync(out_item, item_emb, (size_t)ITEM_NUM * EMB * sizeof(float),
                    cudaMemcpyDeviceToDevice, 0);
}